// round 1
// baseline (speedup 1.0000x reference)
#include <cuda_runtime.h>
#include <math.h>

// Problem constants
#define BATCH 4
#define SEQ   2048
#define DIM   1024
#define NHEAD 16
#define HDIM  64
#define FFDIM 4096
#define MROWS (BATCH*SEQ)   // 8192

// -------------------- scratch (static device globals; no runtime allocs) ---
__device__ float g_h  [(size_t)MROWS * DIM];      // LN outputs (reused)
__device__ float g_qkv[(size_t)MROWS * 3 * DIM];  // qkv projection
__device__ float g_att[(size_t)MROWS * DIM];      // attention output
__device__ float g_x2 [(size_t)MROWS * DIM];      // post-attn residual
__device__ float g_ffn[(size_t)MROWS * FFDIM];    // gelu(fc1)

// -------------------- LayerNorm ------------------------------------------
__global__ void __launch_bounds__(256)
ln_kernel(const float* __restrict__ x, const float* __restrict__ g,
          const float* __restrict__ bta, float* __restrict__ out)
{
    const int row = blockIdx.x;
    const int t = threadIdx.x;
    const float* xr = x + (size_t)row * DIM;

    float4 v = *reinterpret_cast<const float4*>(xr + t * 4);
    float s = v.x + v.y + v.z + v.w;
    float q = v.x * v.x + v.y * v.y + v.z * v.z + v.w * v.w;

    #pragma unroll
    for (int o = 16; o; o >>= 1) {
        s += __shfl_xor_sync(0xffffffffu, s, o);
        q += __shfl_xor_sync(0xffffffffu, q, o);
    }
    __shared__ float red[2][8];
    const int w = t >> 5, l = t & 31;
    if (l == 0) { red[0][w] = s; red[1][w] = q; }
    __syncthreads();
    if (t < 32) {
        s = (t < 8) ? red[0][t] : 0.f;
        q = (t < 8) ? red[1][t] : 0.f;
        #pragma unroll
        for (int o = 4; o; o >>= 1) {
            s += __shfl_xor_sync(0xffffffffu, s, o);
            q += __shfl_xor_sync(0xffffffffu, q, o);
        }
        if (t == 0) { red[0][0] = s; red[1][0] = q; }
    }
    __syncthreads();
    const float mean = red[0][0] * (1.f / DIM);
    const float var  = red[1][0] * (1.f / DIM) - mean * mean;
    const float rstd = rsqrtf(var + 1e-5f);

    float4 gv = *reinterpret_cast<const float4*>(g + t * 4);
    float4 bv = *reinterpret_cast<const float4*>(bta + t * 4);
    float4 o4;
    o4.x = (v.x - mean) * rstd * gv.x + bv.x;
    o4.y = (v.y - mean) * rstd * gv.y + bv.y;
    o4.z = (v.z - mean) * rstd * gv.z + bv.z;
    o4.w = (v.w - mean) * rstd * gv.w + bv.w;
    *reinterpret_cast<float4*>(out + (size_t)row * DIM + t * 4) = o4;
}

// -------------------- SGEMM 128x128x8, 8x8 frags --------------------------
// C[M,N] = A[M,K] @ B[K,N]  (+ epilogue)
enum { EPI_NONE = 0, EPI_BIAS_RESID = 1, EPI_BIAS_GELU = 2 };

template<int EPI>
__global__ void __launch_bounds__(256)
sgemm_kernel(const float* __restrict__ A, const float* __restrict__ B,
             const float* __restrict__ bias, const float* __restrict__ R,
             float* __restrict__ C, int M, int N, int K)
{
    __shared__ float As[8][128];
    __shared__ float Bs[8][128];

    const int tid = threadIdx.x;
    const int tx = tid & 15;        // 16 cols of threads
    const int ty = tid >> 4;        // 16 rows of threads
    const int rowBase = blockIdx.y * 128;
    const int colBase = blockIdx.x * 128;

    const int a_r = tid >> 1;             // 0..127
    const int a_c = (tid & 1) << 2;       // 0 or 4
    const int b_r = tid >> 5;             // 0..7
    const int b_c = (tid & 31) << 2;      // 0..124

    const float* Ap = A + (size_t)(rowBase + a_r) * K + a_c;
    const float* Bp = B + (size_t)b_r * N + colBase + b_c;

    float acc[8][8];
    #pragma unroll
    for (int i = 0; i < 8; i++)
        #pragma unroll
        for (int j = 0; j < 8; j++) acc[i][j] = 0.f;

    for (int kt = 0; kt < K; kt += 8) {
        float4 a4 = *reinterpret_cast<const float4*>(Ap + kt);
        float4 b4 = *reinterpret_cast<const float4*>(Bp + (size_t)kt * N);
        As[a_c + 0][a_r] = a4.x;
        As[a_c + 1][a_r] = a4.y;
        As[a_c + 2][a_r] = a4.z;
        As[a_c + 3][a_r] = a4.w;
        *reinterpret_cast<float4*>(&Bs[b_r][b_c]) = b4;
        __syncthreads();

        #pragma unroll
        for (int k = 0; k < 8; k++) {
            float ar[8], br[8];
            *reinterpret_cast<float4*>(ar)     = *reinterpret_cast<float4*>(&As[k][ty * 8]);
            *reinterpret_cast<float4*>(ar + 4) = *reinterpret_cast<float4*>(&As[k][ty * 8 + 4]);
            *reinterpret_cast<float4*>(br)     = *reinterpret_cast<float4*>(&Bs[k][tx * 8]);
            *reinterpret_cast<float4*>(br + 4) = *reinterpret_cast<float4*>(&Bs[k][tx * 8 + 4]);
            #pragma unroll
            for (int i = 0; i < 8; i++)
                #pragma unroll
                for (int j = 0; j < 8; j++)
                    acc[i][j] = fmaf(ar[i], br[j], acc[i][j]);
        }
        __syncthreads();
    }

    const int col = colBase + tx * 8;
    float bv[8];
    if (EPI != EPI_NONE) {
        *reinterpret_cast<float4*>(bv)     = *reinterpret_cast<const float4*>(bias + col);
        *reinterpret_cast<float4*>(bv + 4) = *reinterpret_cast<const float4*>(bias + col + 4);
    }
    #pragma unroll
    for (int i = 0; i < 8; i++) {
        const size_t off = (size_t)(rowBase + ty * 8 + i) * N + col;
        float o[8];
        #pragma unroll
        for (int j = 0; j < 8; j++) {
            float v = acc[i][j];
            if (EPI == EPI_BIAS_RESID) v += bv[j];
            if (EPI == EPI_BIAS_GELU) {
                v += bv[j];
                v = 0.5f * v * (1.f + erff(v * 0.70710678118654752f));
            }
            o[j] = v;
        }
        if (EPI == EPI_BIAS_RESID) {
            float4 r0 = *reinterpret_cast<const float4*>(R + off);
            float4 r1 = *reinterpret_cast<const float4*>(R + off + 4);
            o[0] += r0.x; o[1] += r0.y; o[2] += r0.z; o[3] += r0.w;
            o[4] += r1.x; o[5] += r1.y; o[6] += r1.z; o[7] += r1.w;
        }
        *reinterpret_cast<float4*>(C + off)     = *reinterpret_cast<float4*>(o);
        *reinterpret_cast<float4*>(C + off + 4) = *reinterpret_cast<float4*>(o + 4);
    }
}

// -------------------- Flash attention (fp32, causal) -----------------------
// grid: (SEQ/64, BATCH*NHEAD), block 256.  qkv: [B*T, 3*DIM], o: [B*T, DIM]
__global__ void __launch_bounds__(256)
flash_kernel(const float* __restrict__ qkv, float* __restrict__ o)
{
    extern __shared__ float sm[];
    float (*Qs)[65] = reinterpret_cast<float(*)[65]>(sm);
    float (*Ks)[65] = reinterpret_cast<float(*)[65]>(sm + 64 * 65);
    float (*Vs)[65] = reinterpret_cast<float(*)[65]>(sm + 2 * 64 * 65);
    float (*Ps)[65] = reinterpret_cast<float(*)[65]>(sm + 3 * 64 * 65);

    const int qb = blockIdx.x;          // query tile 0..31
    const int bh = blockIdx.y;          // 0..63
    const int b = bh >> 4, h = bh & 15;
    const int tid = threadIdx.x;
    const int tx = tid & 15, ty = tid >> 4;

    // tile-load mapping: 4 threads per row, 16 contiguous floats each
    const int lr  = tid >> 2;
    const int lc0 = (tid & 3) * 4;

    const size_t rowQ = (size_t)(b * SEQ + qb * 64 + lr) * (3 * DIM) + h * HDIM;
    #pragma unroll
    for (int i = 0; i < 4; i++) {
        float4 v = *reinterpret_cast<const float4*>(qkv + rowQ + lc0 + i * 16);
        Qs[lr][lc0 + i * 16 + 0] = v.x;
        Qs[lr][lc0 + i * 16 + 1] = v.y;
        Qs[lr][lc0 + i * 16 + 2] = v.z;
        Qs[lr][lc0 + i * 16 + 3] = v.w;
    }

    float m_run[4], l_run[4], accO[4][4];
    #pragma unroll
    for (int i = 0; i < 4; i++) {
        m_run[i] = -1e30f; l_run[i] = 0.f;
        #pragma unroll
        for (int j = 0; j < 4; j++) accO[i][j] = 0.f;
    }
    __syncthreads();

    for (int kb = 0; kb <= qb; kb++) {
        const size_t rowK = (size_t)(b * SEQ + kb * 64 + lr) * (3 * DIM) + DIM + h * HDIM;
        #pragma unroll
        for (int i = 0; i < 4; i++) {
            float4 kv = *reinterpret_cast<const float4*>(qkv + rowK + lc0 + i * 16);
            Ks[lr][lc0 + i * 16 + 0] = kv.x;
            Ks[lr][lc0 + i * 16 + 1] = kv.y;
            Ks[lr][lc0 + i * 16 + 2] = kv.z;
            Ks[lr][lc0 + i * 16 + 3] = kv.w;
            float4 vv = *reinterpret_cast<const float4*>(qkv + rowK + DIM + lc0 + i * 16);
            Vs[lr][lc0 + i * 16 + 0] = vv.x;
            Vs[lr][lc0 + i * 16 + 1] = vv.y;
            Vs[lr][lc0 + i * 16 + 2] = vv.z;
            Vs[lr][lc0 + i * 16 + 3] = vv.w;
        }
        __syncthreads();

        // S = (Q K^T) * scale   — each thread computes a 4x4 patch
        float s[4][4];
        #pragma unroll
        for (int i = 0; i < 4; i++)
            #pragma unroll
            for (int j = 0; j < 4; j++) s[i][j] = 0.f;

        #pragma unroll 8
        for (int d = 0; d < HDIM; d++) {
            float qv[4], kv[4];
            #pragma unroll
            for (int i = 0; i < 4; i++) qv[i] = Qs[ty * 4 + i][d];
            #pragma unroll
            for (int j = 0; j < 4; j++) kv[j] = Ks[tx * 4 + j][d];
            #pragma unroll
            for (int i = 0; i < 4; i++)
                #pragma unroll
                for (int j = 0; j < 4; j++)
                    s[i][j] = fmaf(qv[i], kv[j], s[i][j]);
        }
        #pragma unroll
        for (int i = 0; i < 4; i++)
            #pragma unroll
            for (int j = 0; j < 4; j++) s[i][j] *= 0.125f;   // 1/sqrt(64)
        if (kb == qb) {
            #pragma unroll
            for (int i = 0; i < 4; i++)
                #pragma unroll
                for (int j = 0; j < 4; j++)
                    if (tx * 4 + j > ty * 4 + i) s[i][j] = -1e30f;
        }

        // online softmax per row (16 lanes share a row-group)
        #pragma unroll
        for (int i = 0; i < 4; i++) {
            float mx = fmaxf(fmaxf(s[i][0], s[i][1]), fmaxf(s[i][2], s[i][3]));
            #pragma unroll
            for (int off = 1; off < 16; off <<= 1)
                mx = fmaxf(mx, __shfl_xor_sync(0xffffffffu, mx, off));
            const float mnew = fmaxf(m_run[i], mx);
            const float sc = expf(m_run[i] - mnew);
            float r = 0.f;
            #pragma unroll
            for (int j = 0; j < 4; j++) {
                const float p = expf(s[i][j] - mnew);
                Ps[ty * 4 + i][tx * 4 + j] = p;
                r += p;
            }
            #pragma unroll
            for (int off = 1; off < 16; off <<= 1)
                r += __shfl_xor_sync(0xffffffffu, r, off);
            l_run[i] = l_run[i] * sc + r;
            m_run[i] = mnew;
            #pragma unroll
            for (int j = 0; j < 4; j++) accO[i][j] *= sc;
        }
        __syncthreads();

        // O += P @ V
        #pragma unroll 8
        for (int kk = 0; kk < 64; kk++) {
            float pv[4], vv[4];
            #pragma unroll
            for (int i = 0; i < 4; i++) pv[i] = Ps[ty * 4 + i][kk];
            #pragma unroll
            for (int j = 0; j < 4; j++) vv[j] = Vs[kk][tx * 4 + j];
            #pragma unroll
            for (int i = 0; i < 4; i++)
                #pragma unroll
                for (int j = 0; j < 4; j++)
                    accO[i][j] = fmaf(pv[i], vv[j], accO[i][j]);
        }
        __syncthreads();
    }

    #pragma unroll
    for (int i = 0; i < 4; i++) {
        const float inv = 1.f / l_run[i];
        const size_t off = (size_t)(b * SEQ + qb * 64 + ty * 4 + i) * DIM + h * HDIM + tx * 4;
        float4 o4;
        o4.x = accO[i][0] * inv;
        o4.y = accO[i][1] * inv;
        o4.z = accO[i][2] * inv;
        o4.w = accO[i][3] * inv;
        *reinterpret_cast<float4*>(o + off) = o4;
    }
}

// -------------------- launch ------------------------------------------------
extern "C" void kernel_launch(void* const* d_in, const int* in_sizes, int n_in,
                              void* d_out, int out_size)
{
    (void)in_sizes; (void)n_in; (void)out_size;
    const float* x     = (const float*)d_in[0];
    // d_in[1] = causal mask (known structure; not needed)
    const float* ln1_g = (const float*)d_in[2];
    const float* ln1_b = (const float*)d_in[3];
    const float* ln2_g = (const float*)d_in[4];
    const float* ln2_b = (const float*)d_in[5];
    const float* qkv_w = (const float*)d_in[6];
    const float* out_w = (const float*)d_in[7];
    const float* out_b = (const float*)d_in[8];
    const float* fc1_w = (const float*)d_in[9];
    const float* fc1_b = (const float*)d_in[10];
    const float* fc2_w = (const float*)d_in[11];
    const float* fc2_b = (const float*)d_in[12];
    float* out = (float*)d_out;

    float *h, *qkv, *att, *x2, *ffn;
    cudaGetSymbolAddress((void**)&h,   g_h);
    cudaGetSymbolAddress((void**)&qkv, g_qkv);
    cudaGetSymbolAddress((void**)&att, g_att);
    cudaGetSymbolAddress((void**)&x2,  g_x2);
    cudaGetSymbolAddress((void**)&ffn, g_ffn);

    const int FLASH_SMEM = 4 * 64 * 65 * sizeof(float);   // 66560 B
    cudaFuncSetAttribute(flash_kernel,
                         cudaFuncAttributeMaxDynamicSharedMemorySize, FLASH_SMEM);

    // 1. LN1
    ln_kernel<<<MROWS, 256>>>(x, ln1_g, ln1_b, h);
    // 2. qkv = h @ qkv_w            [8192 x 3072 x 1024]
    sgemm_kernel<EPI_NONE><<<dim3(3 * DIM / 128, MROWS / 128), 256>>>(
        h, qkv_w, nullptr, nullptr, qkv, MROWS, 3 * DIM, DIM);
    // 3. attention
    flash_kernel<<<dim3(SEQ / 64, BATCH * NHEAD), 256, FLASH_SMEM>>>(qkv, att);
    // 4. x2 = x + att @ out_w + out_b   [8192 x 1024 x 1024]
    sgemm_kernel<EPI_BIAS_RESID><<<dim3(DIM / 128, MROWS / 128), 256>>>(
        att, out_w, out_b, x, x2, MROWS, DIM, DIM);
    // 5. LN2
    ln_kernel<<<MROWS, 256>>>(x2, ln2_g, ln2_b, h);
    // 6. ffn = gelu(h @ fc1_w + fc1_b)  [8192 x 4096 x 1024]
    sgemm_kernel<EPI_BIAS_GELU><<<dim3(FFDIM / 128, MROWS / 128), 256>>>(
        h, fc1_w, fc1_b, nullptr, ffn, MROWS, FFDIM, DIM);
    // 7. out = x2 + ffn @ fc2_w + fc2_b [8192 x 1024 x 4096]
    sgemm_kernel<EPI_BIAS_RESID><<<dim3(DIM / 128, MROWS / 128), 256>>>(
        ffn, fc2_w, fc2_b, x2, out, MROWS, DIM, FFDIM);
}

// round 3
// speedup vs baseline: 1.9999x; 1.9999x over previous
#include <cuda_runtime.h>
#include <cuda_bf16.h>
#include <stdint.h>
#include <math.h>

// Problem constants
#define BATCH 4
#define SEQ   2048
#define DIM   1024
#define NHEAD 16
#define HDIM  64
#define FFDIM 4096
#define MROWS (BATCH*SEQ)   // 8192

// ==================== static device scratch (no runtime allocs) ============
__device__ float g_qkv[(size_t)MROWS * 3 * DIM];              // qkv fp32
__device__ float g_x2 [(size_t)MROWS * DIM];                  // post-attn residual fp32
__device__ __nv_bfloat16 g_h_hi [(size_t)MROWS * DIM];        // LN out (hi/lo)
__device__ __nv_bfloat16 g_h_lo [(size_t)MROWS * DIM];
__device__ __nv_bfloat16 g_att_hi[(size_t)MROWS * DIM];       // attention out
__device__ __nv_bfloat16 g_att_lo[(size_t)MROWS * DIM];
__device__ __nv_bfloat16 g_ffn_hi[(size_t)MROWS * FFDIM];     // gelu(fc1)
__device__ __nv_bfloat16 g_ffn_lo[(size_t)MROWS * FFDIM];
// transposed+split weights: [N, K] bf16
__device__ __nv_bfloat16 g_wq_hi[(size_t)3*DIM * DIM];
__device__ __nv_bfloat16 g_wq_lo[(size_t)3*DIM * DIM];
__device__ __nv_bfloat16 g_wo_hi[(size_t)DIM * DIM];
__device__ __nv_bfloat16 g_wo_lo[(size_t)DIM * DIM];
__device__ __nv_bfloat16 g_w1_hi[(size_t)FFDIM * DIM];
__device__ __nv_bfloat16 g_w1_lo[(size_t)FFDIM * DIM];
__device__ __nv_bfloat16 g_w2_hi[(size_t)DIM * FFDIM];
__device__ __nv_bfloat16 g_w2_lo[(size_t)DIM * FFDIM];

// ==================== helpers ==============================================
__device__ __forceinline__ uint32_t smem_u32(const void* p) {
    uint32_t a;
    asm("{ .reg .u64 t; cvta.to.shared.u64 t, %1; cvt.u32.u64 %0, t; }" : "=r"(a) : "l"(p));
    return a;
}

#define CP_ASYNC16(saddr, gptr) \
    asm volatile("cp.async.cg.shared.global [%0], [%1], 16;" \
        :: "r"(saddr), "l"((const void*)(gptr)))
#define CP_COMMIT() asm volatile("cp.async.commit_group;" ::: "memory")
#define CP_WAIT1()  asm volatile("cp.async.wait_group 1;" ::: "memory")
#define CP_WAIT0()  asm volatile("cp.async.wait_group 0;" ::: "memory")

#define LDSM_X4(r0, r1, r2, r3, addr) \
    asm volatile("ldmatrix.sync.aligned.m8n8.x4.shared.b16 {%0,%1,%2,%3}, [%4];" \
        : "=r"(r0), "=r"(r1), "=r"(r2), "=r"(r3) : "r"(addr))

#define MMA_BF16(d, a, b0v, b1v) \
    asm volatile("mma.sync.aligned.m16n8k16.row.col.f32.bf16.bf16.f32 " \
        "{%0,%1,%2,%3}, {%4,%5,%6,%7}, {%8,%9}, {%0,%1,%2,%3};" \
        : "+f"((d)[0]), "+f"((d)[1]), "+f"((d)[2]), "+f"((d)[3]) \
        : "r"((a)[0]), "r"((a)[1]), "r"((a)[2]), "r"((a)[3]), "r"(b0v), "r"(b1v))

__device__ __forceinline__ void split_bf16(float v, __nv_bfloat16& hi, __nv_bfloat16& lo) {
    hi = __float2bfloat16(v);
    lo = __float2bfloat16(v - __bfloat162float(hi));
}

// ==================== weight transpose + split =============================
// W[K,N] fp32  ->  Th/Tl[N,K] bf16
__global__ void __launch_bounds__(256)
wsplit_kernel(const float* __restrict__ W, __nv_bfloat16* __restrict__ Th,
              __nv_bfloat16* __restrict__ Tl, int K, int N)
{
    __shared__ float tile[32][33];
    const int bx = blockIdx.x, by = blockIdx.y;
    const int tx = threadIdx.x & 31, ty = threadIdx.x >> 5;  // 32 x 8
    #pragma unroll
    for (int r = 0; r < 32; r += 8) {
        const int k = by * 32 + ty + r, n = bx * 32 + tx;
        tile[ty + r][tx] = W[(size_t)k * N + n];
    }
    __syncthreads();
    #pragma unroll
    for (int r = 0; r < 32; r += 8) {
        const int n = bx * 32 + ty + r, k = by * 32 + tx;
        const float v = tile[tx][ty + r];
        __nv_bfloat16 hi, lo;
        split_bf16(v, hi, lo);
        Th[(size_t)n * K + k] = hi;
        Tl[(size_t)n * K + k] = lo;
    }
}

// ==================== LayerNorm (emits bf16 hi/lo) =========================
__global__ void __launch_bounds__(256)
ln_kernel(const float* __restrict__ x, const float* __restrict__ g,
          const float* __restrict__ bta,
          __nv_bfloat16* __restrict__ ohi, __nv_bfloat16* __restrict__ olo)
{
    const int row = blockIdx.x;
    const int t = threadIdx.x;
    const float* xr = x + (size_t)row * DIM;

    float4 v = *reinterpret_cast<const float4*>(xr + t * 4);
    float s = v.x + v.y + v.z + v.w;
    float q = v.x * v.x + v.y * v.y + v.z * v.z + v.w * v.w;

    #pragma unroll
    for (int o = 16; o; o >>= 1) {
        s += __shfl_xor_sync(0xffffffffu, s, o);
        q += __shfl_xor_sync(0xffffffffu, q, o);
    }
    __shared__ float red[2][8];
    const int w = t >> 5, l = t & 31;
    if (l == 0) { red[0][w] = s; red[1][w] = q; }
    __syncthreads();
    if (t < 32) {
        s = (t < 8) ? red[0][t] : 0.f;
        q = (t < 8) ? red[1][t] : 0.f;
        #pragma unroll
        for (int o = 4; o; o >>= 1) {
            s += __shfl_xor_sync(0xffffffffu, s, o);
            q += __shfl_xor_sync(0xffffffffu, q, o);
        }
        if (t == 0) { red[0][0] = s; red[1][0] = q; }
    }
    __syncthreads();
    const float mean = red[0][0] * (1.f / DIM);
    const float var  = red[1][0] * (1.f / DIM) - mean * mean;
    const float rstd = rsqrtf(var + 1e-5f);

    float4 gv = *reinterpret_cast<const float4*>(g + t * 4);
    float4 bv = *reinterpret_cast<const float4*>(bta + t * 4);
    float o0 = (v.x - mean) * rstd * gv.x + bv.x;
    float o1 = (v.y - mean) * rstd * gv.y + bv.y;
    float o2 = (v.z - mean) * rstd * gv.z + bv.z;
    float o3 = (v.w - mean) * rstd * gv.w + bv.w;

    __nv_bfloat16 h0, h1, h2, h3, l0, l1, l2, l3;
    split_bf16(o0, h0, l0); split_bf16(o1, h1, l1);
    split_bf16(o2, h2, l2); split_bf16(o3, h3, l3);
    const size_t off = (size_t)row * DIM + t * 4;
    *reinterpret_cast<__nv_bfloat162*>(ohi + off)     = __halves2bfloat162(h0, h1);
    *reinterpret_cast<__nv_bfloat162*>(ohi + off + 2) = __halves2bfloat162(h2, h3);
    *reinterpret_cast<__nv_bfloat162*>(olo + off)     = __halves2bfloat162(l0, l1);
    *reinterpret_cast<__nv_bfloat162*>(olo + off + 2) = __halves2bfloat162(l2, l3);
}

// ==================== mma.sync GEMM ========================================
// C[M,N] = (Ah+Al)[M,K] @ (Bh+Bl)^T  where B arrays are [N,K] bf16 K-major.
// 3-pass split: hh + hl + lh into fp32 accumulators.
// CTA 128x128, BK=32, 8 warps x (64x32), cp.async double buffer.
enum { EPI_NONE = 0, EPI_BIAS_RESID = 1, EPI_BIAS_GELU = 2 };

// smem: per stage 4 tiles of 128 rows x 40 bf16 (80B padded rows) = 10240B each
#define TILE_BYTES   10240
#define STAGE_BYTES  (4 * TILE_BYTES)       // 40960
#define GEMM_SMEM    (2 * STAGE_BYTES)      // 81920
#define OFF_A_HI 0
#define OFF_A_LO 10240
#define OFF_B_HI 20480
#define OFF_B_LO 30720

template<int EPI>
__global__ void __launch_bounds__(256, 2)
tc_gemm_kernel(const __nv_bfloat16* __restrict__ Ah, const __nv_bfloat16* __restrict__ Al,
               const __nv_bfloat16* __restrict__ Bh, const __nv_bfloat16* __restrict__ Bl,
               const float* __restrict__ bias, const float* __restrict__ R,
               float* __restrict__ Cf,
               __nv_bfloat16* __restrict__ Ch, __nv_bfloat16* __restrict__ Cl,
               int N, int K)
{
    extern __shared__ char smem[];
    const uint32_t sb = smem_u32(smem);
    const int tid = threadIdx.x;
    const int lane = tid & 31, wid = tid >> 5;
    const int warp_m = wid >> 2;          // 0..1
    const int warp_n = wid & 3;           // 0..3
    const int rowBase = blockIdx.y * 128;
    const int colBase = blockIdx.x * 128;

    float acc[4][4][4];
    #pragma unroll
    for (int mt = 0; mt < 4; mt++)
        #pragma unroll
        for (int nt = 0; nt < 4; nt++)
            #pragma unroll
            for (int r = 0; r < 4; r++) acc[mt][nt][r] = 0.f;

    // ------- async stage loader -------
    auto load_stage = [&](int c, int stage) {
        const int kbase = c * 32;
        const uint32_t stbase = sb + stage * STAGE_BYTES;
        #pragma unroll
        for (int i = 0; i < 2; i++) {
            const int qd = tid + i * 256;         // 0..511
            const int row = qd >> 2;              // 0..127
            const int q = qd & 3;                 // 16B quad within 64B of data
            const uint32_t so = stbase + row * 80 + q * 16;
            const size_t ao = (size_t)(rowBase + row) * K + kbase + q * 8;
            const size_t bo = (size_t)(colBase + row) * K + kbase + q * 8;
            CP_ASYNC16(so + OFF_A_HI, Ah + ao);
            CP_ASYNC16(so + OFF_A_LO, Al + ao);
            CP_ASYNC16(so + OFF_B_HI, Bh + bo);
            CP_ASYNC16(so + OFF_B_LO, Bl + bo);
        }
        CP_COMMIT();
    };

    const int nChunks = K >> 5;
    load_stage(0, 0);

    // ldmatrix lane address components (constant across chunks)
    const uint32_t a_row = warp_m * 64 + (lane & 15);
    const uint32_t a_kadd = (lane >> 4) * 8;
    const uint32_t b_row = warp_n * 32 + (lane & 7) + ((lane >> 4) << 3);
    const uint32_t b_kadd = ((lane >> 3) & 1) * 8;

    for (int c = 0; c < nChunks; c++) {
        if (c + 1 < nChunks) { load_stage(c + 1, (c + 1) & 1); CP_WAIT1(); }
        else { CP_WAIT0(); }
        __syncthreads();

        const uint32_t st = sb + (c & 1) * STAGE_BYTES;

        #pragma unroll
        for (int ks = 0; ks < 2; ks++) {
            const uint32_t a_off = a_row * 80 + (ks * 16 + a_kadd) * 2;
            const uint32_t b_off = b_row * 80 + (ks * 16 + b_kadd) * 2;

            uint32_t a[4][4], bh[8], bl[8];
            // A_hi fragments (4 m-tiles)
            #pragma unroll
            for (int mt = 0; mt < 4; mt++)
                LDSM_X4(a[mt][0], a[mt][1], a[mt][2], a[mt][3],
                        st + OFF_A_HI + a_off + mt * (16 * 80));
            // B_hi fragments (4 n-tiles in 2 x4 loads)
            LDSM_X4(bh[0], bh[1], bh[2], bh[3], st + OFF_B_HI + b_off);
            LDSM_X4(bh[4], bh[5], bh[6], bh[7], st + OFF_B_HI + b_off + 16 * 80);
            // B_lo fragments
            LDSM_X4(bl[0], bl[1], bl[2], bl[3], st + OFF_B_LO + b_off);
            LDSM_X4(bl[4], bl[5], bl[6], bl[7], st + OFF_B_LO + b_off + 16 * 80);

            // pass hh + hl
            #pragma unroll
            for (int mt = 0; mt < 4; mt++)
                #pragma unroll
                for (int nt = 0; nt < 4; nt++) {
                    MMA_BF16(acc[mt][nt], a[mt], bh[nt * 2], bh[nt * 2 + 1]);
                    MMA_BF16(acc[mt][nt], a[mt], bl[nt * 2], bl[nt * 2 + 1]);
                }
            // A_lo fragments (reuse regs), pass lh
            #pragma unroll
            for (int mt = 0; mt < 4; mt++)
                LDSM_X4(a[mt][0], a[mt][1], a[mt][2], a[mt][3],
                        st + OFF_A_LO + a_off + mt * (16 * 80));
            #pragma unroll
            for (int mt = 0; mt < 4; mt++)
                #pragma unroll
                for (int nt = 0; nt < 4; nt++)
                    MMA_BF16(acc[mt][nt], a[mt], bh[nt * 2], bh[nt * 2 + 1]);
        }
        __syncthreads();
    }

    // ------- epilogue -------
    #pragma unroll
    for (int mt = 0; mt < 4; mt++) {
        const int r0 = rowBase + warp_m * 64 + mt * 16 + (lane >> 2);
        const int r1 = r0 + 8;
        #pragma unroll
        for (int nt = 0; nt < 4; nt++) {
            const int col = colBase + warp_n * 32 + nt * 8 + (lane & 3) * 2;
            float v0 = acc[mt][nt][0], v1 = acc[mt][nt][1];
            float v2 = acc[mt][nt][2], v3 = acc[mt][nt][3];
            if (EPI != EPI_NONE) {
                const float b0 = __ldg(bias + col), b1 = __ldg(bias + col + 1);
                v0 += b0; v1 += b1; v2 += b0; v3 += b1;
            }
            if (EPI == EPI_BIAS_GELU) {
                v0 = 0.5f * v0 * (1.f + erff(v0 * 0.70710678118654752f));
                v1 = 0.5f * v1 * (1.f + erff(v1 * 0.70710678118654752f));
                v2 = 0.5f * v2 * (1.f + erff(v2 * 0.70710678118654752f));
                v3 = 0.5f * v3 * (1.f + erff(v3 * 0.70710678118654752f));
                __nv_bfloat16 h0, h1, h2, h3, l0, l1, l2, l3;
                split_bf16(v0, h0, l0); split_bf16(v1, h1, l1);
                split_bf16(v2, h2, l2); split_bf16(v3, h3, l3);
                *reinterpret_cast<__nv_bfloat162*>(Ch + (size_t)r0 * N + col) = __halves2bfloat162(h0, h1);
                *reinterpret_cast<__nv_bfloat162*>(Cl + (size_t)r0 * N + col) = __halves2bfloat162(l0, l1);
                *reinterpret_cast<__nv_bfloat162*>(Ch + (size_t)r1 * N + col) = __halves2bfloat162(h2, h3);
                *reinterpret_cast<__nv_bfloat162*>(Cl + (size_t)r1 * N + col) = __halves2bfloat162(l2, l3);
            } else {
                if (EPI == EPI_BIAS_RESID) {
                    const float2 ra = *reinterpret_cast<const float2*>(R + (size_t)r0 * N + col);
                    const float2 rb = *reinterpret_cast<const float2*>(R + (size_t)r1 * N + col);
                    v0 += ra.x; v1 += ra.y; v2 += rb.x; v3 += rb.y;
                }
                float2 p0; p0.x = v0; p0.y = v1;
                float2 p1; p1.x = v2; p1.y = v3;
                *reinterpret_cast<float2*>(Cf + (size_t)r0 * N + col) = p0;
                *reinterpret_cast<float2*>(Cf + (size_t)r1 * N + col) = p1;
            }
        }
    }
}

// ==================== Flash attention (fp32, causal; bf16 hi/lo out) -------
__global__ void __launch_bounds__(256)
flash_kernel(const float* __restrict__ qkv,
             __nv_bfloat16* __restrict__ ohi, __nv_bfloat16* __restrict__ olo)
{
    extern __shared__ float sm[];
    float (*Qs)[65] = reinterpret_cast<float(*)[65]>(sm);
    float (*Ks)[65] = reinterpret_cast<float(*)[65]>(sm + 64 * 65);
    float (*Vs)[65] = reinterpret_cast<float(*)[65]>(sm + 2 * 64 * 65);
    float (*Ps)[65] = reinterpret_cast<float(*)[65]>(sm + 3 * 64 * 65);

    const int qb = blockIdx.x;
    const int bh = blockIdx.y;
    const int b = bh >> 4, h = bh & 15;
    const int tid = threadIdx.x;
    const int tx = tid & 15, ty = tid >> 4;

    const int lr  = tid >> 2;
    const int lc0 = (tid & 3) * 4;

    const size_t rowQ = (size_t)(b * SEQ + qb * 64 + lr) * (3 * DIM) + h * HDIM;
    #pragma unroll
    for (int i = 0; i < 4; i++) {
        float4 v = *reinterpret_cast<const float4*>(qkv + rowQ + lc0 + i * 16);
        Qs[lr][lc0 + i * 16 + 0] = v.x;
        Qs[lr][lc0 + i * 16 + 1] = v.y;
        Qs[lr][lc0 + i * 16 + 2] = v.z;
        Qs[lr][lc0 + i * 16 + 3] = v.w;
    }

    float m_run[4], l_run[4], accO[4][4];
    #pragma unroll
    for (int i = 0; i < 4; i++) {
        m_run[i] = -1e30f; l_run[i] = 0.f;
        #pragma unroll
        for (int j = 0; j < 4; j++) accO[i][j] = 0.f;
    }
    __syncthreads();

    for (int kb = 0; kb <= qb; kb++) {
        const size_t rowK = (size_t)(b * SEQ + kb * 64 + lr) * (3 * DIM) + DIM + h * HDIM;
        #pragma unroll
        for (int i = 0; i < 4; i++) {
            float4 kv = *reinterpret_cast<const float4*>(qkv + rowK + lc0 + i * 16);
            Ks[lr][lc0 + i * 16 + 0] = kv.x;
            Ks[lr][lc0 + i * 16 + 1] = kv.y;
            Ks[lr][lc0 + i * 16 + 2] = kv.z;
            Ks[lr][lc0 + i * 16 + 3] = kv.w;
            float4 vv = *reinterpret_cast<const float4*>(qkv + rowK + DIM + lc0 + i * 16);
            Vs[lr][lc0 + i * 16 + 0] = vv.x;
            Vs[lr][lc0 + i * 16 + 1] = vv.y;
            Vs[lr][lc0 + i * 16 + 2] = vv.z;
            Vs[lr][lc0 + i * 16 + 3] = vv.w;
        }
        __syncthreads();

        float s[4][4];
        #pragma unroll
        for (int i = 0; i < 4; i++)
            #pragma unroll
            for (int j = 0; j < 4; j++) s[i][j] = 0.f;

        #pragma unroll 8
        for (int d = 0; d < HDIM; d++) {
            float qv[4], kv[4];
            #pragma unroll
            for (int i = 0; i < 4; i++) qv[i] = Qs[ty * 4 + i][d];
            #pragma unroll
            for (int j = 0; j < 4; j++) kv[j] = Ks[tx * 4 + j][d];
            #pragma unroll
            for (int i = 0; i < 4; i++)
                #pragma unroll
                for (int j = 0; j < 4; j++)
                    s[i][j] = fmaf(qv[i], kv[j], s[i][j]);
        }
        #pragma unroll
        for (int i = 0; i < 4; i++)
            #pragma unroll
            for (int j = 0; j < 4; j++) s[i][j] *= 0.125f;
        if (kb == qb) {
            #pragma unroll
            for (int i = 0; i < 4; i++)
                #pragma unroll
                for (int j = 0; j < 4; j++)
                    if (tx * 4 + j > ty * 4 + i) s[i][j] = -1e30f;
        }

        #pragma unroll
        for (int i = 0; i < 4; i++) {
            float mx = fmaxf(fmaxf(s[i][0], s[i][1]), fmaxf(s[i][2], s[i][3]));
            #pragma unroll
            for (int off = 1; off < 16; off <<= 1)
                mx = fmaxf(mx, __shfl_xor_sync(0xffffffffu, mx, off));
            const float mnew = fmaxf(m_run[i], mx);
            const float sc = expf(m_run[i] - mnew);
            float r = 0.f;
            #pragma unroll
            for (int j = 0; j < 4; j++) {
                const float p = expf(s[i][j] - mnew);
                Ps[ty * 4 + i][tx * 4 + j] = p;
                r += p;
            }
            #pragma unroll
            for (int off = 1; off < 16; off <<= 1)
                r += __shfl_xor_sync(0xffffffffu, r, off);
            l_run[i] = l_run[i] * sc + r;
            m_run[i] = mnew;
            #pragma unroll
            for (int j = 0; j < 4; j++) accO[i][j] *= sc;
        }
        __syncthreads();

        #pragma unroll 8
        for (int kk = 0; kk < 64; kk++) {
            float pv[4], vv[4];
            #pragma unroll
            for (int i = 0; i < 4; i++) pv[i] = Ps[ty * 4 + i][kk];
            #pragma unroll
            for (int j = 0; j < 4; j++) vv[j] = Vs[kk][tx * 4 + j];
            #pragma unroll
            for (int i = 0; i < 4; i++)
                #pragma unroll
                for (int j = 0; j < 4; j++)
                    accO[i][j] = fmaf(pv[i], vv[j], accO[i][j]);
        }
        __syncthreads();
    }

    #pragma unroll
    for (int i = 0; i < 4; i++) {
        const float inv = 1.f / l_run[i];
        const size_t off = (size_t)(b * SEQ + qb * 64 + ty * 4 + i) * DIM + h * HDIM + tx * 4;
        float v0 = accO[i][0] * inv, v1 = accO[i][1] * inv;
        float v2 = accO[i][2] * inv, v3 = accO[i][3] * inv;
        __nv_bfloat16 h0, h1, h2, h3, l0, l1, l2, l3;
        split_bf16(v0, h0, l0); split_bf16(v1, h1, l1);
        split_bf16(v2, h2, l2); split_bf16(v3, h3, l3);
        *reinterpret_cast<__nv_bfloat162*>(ohi + off)     = __halves2bfloat162(h0, h1);
        *reinterpret_cast<__nv_bfloat162*>(ohi + off + 2) = __halves2bfloat162(h2, h3);
        *reinterpret_cast<__nv_bfloat162*>(olo + off)     = __halves2bfloat162(l0, l1);
        *reinterpret_cast<__nv_bfloat162*>(olo + off + 2) = __halves2bfloat162(l2, l3);
    }
}

// ==================== launch ================================================
extern "C" void kernel_launch(void* const* d_in, const int* in_sizes, int n_in,
                              void* d_out, int out_size)
{
    (void)in_sizes; (void)n_in; (void)out_size;
    const float* x     = (const float*)d_in[0];
    const float* ln1_g = (const float*)d_in[2];
    const float* ln1_b = (const float*)d_in[3];
    const float* ln2_g = (const float*)d_in[4];
    const float* ln2_b = (const float*)d_in[5];
    const float* qkv_w = (const float*)d_in[6];
    const float* out_w = (const float*)d_in[7];
    const float* out_b = (const float*)d_in[8];
    const float* fc1_w = (const float*)d_in[9];
    const float* fc1_b = (const float*)d_in[10];
    const float* fc2_w = (const float*)d_in[11];
    const float* fc2_b = (const float*)d_in[12];
    float* out = (float*)d_out;

    float *qkv, *x2;
    __nv_bfloat16 *h_hi, *h_lo, *att_hi, *att_lo, *ffn_hi, *ffn_lo;
    __nv_bfloat16 *wq_hi, *wq_lo, *wo_hi, *wo_lo, *w1_hi, *w1_lo, *w2_hi, *w2_lo;
    cudaGetSymbolAddress((void**)&qkv,    g_qkv);
    cudaGetSymbolAddress((void**)&x2,     g_x2);
    cudaGetSymbolAddress((void**)&h_hi,   g_h_hi);
    cudaGetSymbolAddress((void**)&h_lo,   g_h_lo);
    cudaGetSymbolAddress((void**)&att_hi, g_att_hi);
    cudaGetSymbolAddress((void**)&att_lo, g_att_lo);
    cudaGetSymbolAddress((void**)&ffn_hi, g_ffn_hi);
    cudaGetSymbolAddress((void**)&ffn_lo, g_ffn_lo);
    cudaGetSymbolAddress((void**)&wq_hi,  g_wq_hi);
    cudaGetSymbolAddress((void**)&wq_lo,  g_wq_lo);
    cudaGetSymbolAddress((void**)&wo_hi,  g_wo_hi);
    cudaGetSymbolAddress((void**)&wo_lo,  g_wo_lo);
    cudaGetSymbolAddress((void**)&w1_hi,  g_w1_hi);
    cudaGetSymbolAddress((void**)&w1_lo,  g_w1_lo);
    cudaGetSymbolAddress((void**)&w2_hi,  g_w2_hi);
    cudaGetSymbolAddress((void**)&w2_lo,  g_w2_lo);

    const int FLASH_SMEM = 4 * 64 * 65 * sizeof(float);
    cudaFuncSetAttribute(flash_kernel,
                         cudaFuncAttributeMaxDynamicSharedMemorySize, FLASH_SMEM);
    cudaFuncSetAttribute(tc_gemm_kernel<EPI_NONE>,
                         cudaFuncAttributeMaxDynamicSharedMemorySize, GEMM_SMEM);
    cudaFuncSetAttribute(tc_gemm_kernel<EPI_BIAS_RESID>,
                         cudaFuncAttributeMaxDynamicSharedMemorySize, GEMM_SMEM);
    cudaFuncSetAttribute(tc_gemm_kernel<EPI_BIAS_GELU>,
                         cudaFuncAttributeMaxDynamicSharedMemorySize, GEMM_SMEM);

    // 0. weight transpose + split
    wsplit_kernel<<<dim3(3 * DIM / 32, DIM / 32), 256>>>(qkv_w, wq_hi, wq_lo, DIM, 3 * DIM);
    wsplit_kernel<<<dim3(DIM / 32, DIM / 32), 256>>>(out_w, wo_hi, wo_lo, DIM, DIM);
    wsplit_kernel<<<dim3(FFDIM / 32, DIM / 32), 256>>>(fc1_w, w1_hi, w1_lo, DIM, FFDIM);
    wsplit_kernel<<<dim3(DIM / 32, FFDIM / 32), 256>>>(fc2_w, w2_hi, w2_lo, FFDIM, DIM);

    // 1. LN1 -> h (bf16 hi/lo)
    ln_kernel<<<MROWS, 256>>>(x, ln1_g, ln1_b, h_hi, h_lo);
    // 2. qkv = h @ qkv_w  [8192 x 3072 x 1024]  (fp32 out)
    tc_gemm_kernel<EPI_NONE><<<dim3(3 * DIM / 128, MROWS / 128), 256, GEMM_SMEM>>>(
        h_hi, h_lo, wq_hi, wq_lo, nullptr, nullptr, qkv, nullptr, nullptr, 3 * DIM, DIM);
    // 3. attention -> att (bf16 hi/lo)
    flash_kernel<<<dim3(SEQ / 64, BATCH * NHEAD), 256, FLASH_SMEM>>>(qkv, att_hi, att_lo);
    // 4. x2 = x + att @ out_w + out_b  [8192 x 1024 x 1024]
    tc_gemm_kernel<EPI_BIAS_RESID><<<dim3(DIM / 128, MROWS / 128), 256, GEMM_SMEM>>>(
        att_hi, att_lo, wo_hi, wo_lo, out_b, x, x2, nullptr, nullptr, DIM, DIM);
    // 5. LN2 -> h (bf16 hi/lo)
    ln_kernel<<<MROWS, 256>>>(x2, ln2_g, ln2_b, h_hi, h_lo);
    // 6. ffn = gelu(h @ fc1_w + fc1_b)  [8192 x 4096 x 1024]  (bf16 hi/lo out)
    tc_gemm_kernel<EPI_BIAS_GELU><<<dim3(FFDIM / 128, MROWS / 128), 256, GEMM_SMEM>>>(
        h_hi, h_lo, w1_hi, w1_lo, fc1_b, nullptr, nullptr, ffn_hi, ffn_lo, FFDIM, DIM);
    // 7. out = x2 + ffn @ fc2_w + fc2_b  [8192 x 1024 x 4096]
    tc_gemm_kernel<EPI_BIAS_RESID><<<dim3(DIM / 128, MROWS / 128), 256, GEMM_SMEM>>>(
        ffn_hi, ffn_lo, w2_hi, w2_lo, fc2_b, x2, out, nullptr, nullptr, DIM, FFDIM);
}

// round 4
// speedup vs baseline: 2.8481x; 1.4241x over previous
#include <cuda_runtime.h>
#include <cuda_bf16.h>
#include <stdint.h>
#include <math.h>

// Problem constants
#define BATCH 4
#define SEQ   2048
#define DIM   1024
#define NHEAD 16
#define HDIM  64
#define FFDIM 4096
#define MROWS (BATCH*SEQ)   // 8192

// ==================== static device scratch (no runtime allocs) ============
__device__ float g_x2 [(size_t)MROWS * DIM];                  // post-attn residual fp32
__device__ __nv_bfloat16 g_qkv_hi[(size_t)MROWS * 3 * DIM];   // split qkv (q pre-scaled 1/8)
__device__ __nv_bfloat16 g_qkv_lo[(size_t)MROWS * 3 * DIM];
__device__ __nv_bfloat16 g_h_hi [(size_t)MROWS * DIM];        // LN out (hi/lo)
__device__ __nv_bfloat16 g_h_lo [(size_t)MROWS * DIM];
__device__ __nv_bfloat16 g_att_hi[(size_t)MROWS * DIM];       // attention out
__device__ __nv_bfloat16 g_att_lo[(size_t)MROWS * DIM];
__device__ __nv_bfloat16 g_ffn_hi[(size_t)MROWS * FFDIM];     // gelu(fc1)
__device__ __nv_bfloat16 g_ffn_lo[(size_t)MROWS * FFDIM];
// transposed+split weights: [N, K] bf16
__device__ __nv_bfloat16 g_wq_hi[(size_t)3*DIM * DIM];
__device__ __nv_bfloat16 g_wq_lo[(size_t)3*DIM * DIM];
__device__ __nv_bfloat16 g_wo_hi[(size_t)DIM * DIM];
__device__ __nv_bfloat16 g_wo_lo[(size_t)DIM * DIM];
__device__ __nv_bfloat16 g_w1_hi[(size_t)FFDIM * DIM];
__device__ __nv_bfloat16 g_w1_lo[(size_t)FFDIM * DIM];
__device__ __nv_bfloat16 g_w2_hi[(size_t)DIM * FFDIM];
__device__ __nv_bfloat16 g_w2_lo[(size_t)DIM * FFDIM];

// ==================== helpers ==============================================
__device__ __forceinline__ uint32_t smem_u32(const void* p) {
    uint32_t a;
    asm("{ .reg .u64 t; cvta.to.shared.u64 t, %1; cvt.u32.u64 %0, t; }" : "=r"(a) : "l"(p));
    return a;
}

#define CP_ASYNC16(saddr, gptr) \
    asm volatile("cp.async.cg.shared.global [%0], [%1], 16;" \
        :: "r"(saddr), "l"((const void*)(gptr)))
#define CP_COMMIT() asm volatile("cp.async.commit_group;" ::: "memory")
#define CP_WAIT1()  asm volatile("cp.async.wait_group 1;" ::: "memory")
#define CP_WAIT0()  asm volatile("cp.async.wait_group 0;" ::: "memory")

#define LDSM_X4(r0, r1, r2, r3, addr) \
    asm volatile("ldmatrix.sync.aligned.m8n8.x4.shared.b16 {%0,%1,%2,%3}, [%4];" \
        : "=r"(r0), "=r"(r1), "=r"(r2), "=r"(r3) : "r"(addr))

#define LDSM_X4_T(r0, r1, r2, r3, addr) \
    asm volatile("ldmatrix.sync.aligned.m8n8.x4.trans.shared.b16 {%0,%1,%2,%3}, [%4];" \
        : "=r"(r0), "=r"(r1), "=r"(r2), "=r"(r3) : "r"(addr))

#define MMA_BF16(d, a, b0v, b1v) \
    asm volatile("mma.sync.aligned.m16n8k16.row.col.f32.bf16.bf16.f32 " \
        "{%0,%1,%2,%3}, {%4,%5,%6,%7}, {%8,%9}, {%0,%1,%2,%3};" \
        : "+f"((d)[0]), "+f"((d)[1]), "+f"((d)[2]), "+f"((d)[3]) \
        : "r"((a)[0]), "r"((a)[1]), "r"((a)[2]), "r"((a)[3]), "r"(b0v), "r"(b1v))

__device__ __forceinline__ void split_bf16(float v, __nv_bfloat16& hi, __nv_bfloat16& lo) {
    hi = __float2bfloat16(v);
    lo = __float2bfloat16(v - __bfloat162float(hi));
}

__device__ __forceinline__ void pack_split2(float x, float y, uint32_t& hi, uint32_t& lo) {
    __nv_bfloat16 xh, xl, yh, yl;
    split_bf16(x, xh, xl);
    split_bf16(y, yh, yl);
    __nv_bfloat162 h2 = __halves2bfloat162(xh, yh);
    __nv_bfloat162 l2 = __halves2bfloat162(xl, yl);
    hi = *reinterpret_cast<uint32_t*>(&h2);
    lo = *reinterpret_cast<uint32_t*>(&l2);
}

// ==================== weight transpose + split =============================
// W[K,N] fp32  ->  Th/Tl[N,K] bf16
__global__ void __launch_bounds__(256)
wsplit_kernel(const float* __restrict__ W, __nv_bfloat16* __restrict__ Th,
              __nv_bfloat16* __restrict__ Tl, int K, int N)
{
    __shared__ float tile[32][33];
    const int bx = blockIdx.x, by = blockIdx.y;
    const int tx = threadIdx.x & 31, ty = threadIdx.x >> 5;  // 32 x 8
    #pragma unroll
    for (int r = 0; r < 32; r += 8) {
        const int k = by * 32 + ty + r, n = bx * 32 + tx;
        tile[ty + r][tx] = W[(size_t)k * N + n];
    }
    __syncthreads();
    #pragma unroll
    for (int r = 0; r < 32; r += 8) {
        const int n = bx * 32 + ty + r, k = by * 32 + tx;
        const float v = tile[tx][ty + r];
        __nv_bfloat16 hi, lo;
        split_bf16(v, hi, lo);
        Th[(size_t)n * K + k] = hi;
        Tl[(size_t)n * K + k] = lo;
    }
}

// ==================== LayerNorm (emits bf16 hi/lo) =========================
__global__ void __launch_bounds__(256)
ln_kernel(const float* __restrict__ x, const float* __restrict__ g,
          const float* __restrict__ bta,
          __nv_bfloat16* __restrict__ ohi, __nv_bfloat16* __restrict__ olo)
{
    const int row = blockIdx.x;
    const int t = threadIdx.x;
    const float* xr = x + (size_t)row * DIM;

    float4 v = *reinterpret_cast<const float4*>(xr + t * 4);
    float s = v.x + v.y + v.z + v.w;
    float q = v.x * v.x + v.y * v.y + v.z * v.z + v.w * v.w;

    #pragma unroll
    for (int o = 16; o; o >>= 1) {
        s += __shfl_xor_sync(0xffffffffu, s, o);
        q += __shfl_xor_sync(0xffffffffu, q, o);
    }
    __shared__ float red[2][8];
    const int w = t >> 5, l = t & 31;
    if (l == 0) { red[0][w] = s; red[1][w] = q; }
    __syncthreads();
    if (t < 32) {
        s = (t < 8) ? red[0][t] : 0.f;
        q = (t < 8) ? red[1][t] : 0.f;
        #pragma unroll
        for (int o = 4; o; o >>= 1) {
            s += __shfl_xor_sync(0xffffffffu, s, o);
            q += __shfl_xor_sync(0xffffffffu, q, o);
        }
        if (t == 0) { red[0][0] = s; red[1][0] = q; }
    }
    __syncthreads();
    const float mean = red[0][0] * (1.f / DIM);
    const float var  = red[1][0] * (1.f / DIM) - mean * mean;
    const float rstd = rsqrtf(var + 1e-5f);

    float4 gv = *reinterpret_cast<const float4*>(g + t * 4);
    float4 bv = *reinterpret_cast<const float4*>(bta + t * 4);
    float o0 = (v.x - mean) * rstd * gv.x + bv.x;
    float o1 = (v.y - mean) * rstd * gv.y + bv.y;
    float o2 = (v.z - mean) * rstd * gv.z + bv.z;
    float o3 = (v.w - mean) * rstd * gv.w + bv.w;

    __nv_bfloat16 h0, h1, h2, h3, l0, l1, l2, l3;
    split_bf16(o0, h0, l0); split_bf16(o1, h1, l1);
    split_bf16(o2, h2, l2); split_bf16(o3, h3, l3);
    const size_t off = (size_t)row * DIM + t * 4;
    *reinterpret_cast<__nv_bfloat162*>(ohi + off)     = __halves2bfloat162(h0, h1);
    *reinterpret_cast<__nv_bfloat162*>(ohi + off + 2) = __halves2bfloat162(h2, h3);
    *reinterpret_cast<__nv_bfloat162*>(olo + off)     = __halves2bfloat162(l0, l1);
    *reinterpret_cast<__nv_bfloat162*>(olo + off + 2) = __halves2bfloat162(l2, l3);
}

// ==================== mma.sync GEMM ========================================
// C[M,N] = (Ah+Al)[M,K] @ (Bh+Bl)^T  where B arrays are [N,K] bf16 K-major.
// 3-pass split: hh + hl + lh into fp32 accumulators.
// CTA 128x128, BK=32, 8 warps x (64x32), cp.async double buffer.
enum { EPI_NONE = 0, EPI_BIAS_RESID = 1, EPI_BIAS_GELU = 2, EPI_QKV = 3 };

// smem: per stage 4 tiles of 128 rows x 40 bf16 (80B padded rows) = 10240B each
#define TILE_BYTES   10240
#define STAGE_BYTES  (4 * TILE_BYTES)       // 40960
#define GEMM_SMEM    (2 * STAGE_BYTES)      // 81920
#define OFF_A_HI 0
#define OFF_A_LO 10240
#define OFF_B_HI 20480
#define OFF_B_LO 30720

template<int EPI>
__global__ void __launch_bounds__(256, 2)
tc_gemm_kernel(const __nv_bfloat16* __restrict__ Ah, const __nv_bfloat16* __restrict__ Al,
               const __nv_bfloat16* __restrict__ Bh, const __nv_bfloat16* __restrict__ Bl,
               const float* __restrict__ bias, const float* __restrict__ R,
               float* __restrict__ Cf,
               __nv_bfloat16* __restrict__ Ch, __nv_bfloat16* __restrict__ Cl,
               int N, int K)
{
    extern __shared__ char smem[];
    const uint32_t sb = smem_u32(smem);
    const int tid = threadIdx.x;
    const int lane = tid & 31, wid = tid >> 5;
    const int warp_m = wid >> 2;          // 0..1
    const int warp_n = wid & 3;           // 0..3
    const int rowBase = blockIdx.y * 128;
    const int colBase = blockIdx.x * 128;

    float acc[4][4][4];
    #pragma unroll
    for (int mt = 0; mt < 4; mt++)
        #pragma unroll
        for (int nt = 0; nt < 4; nt++)
            #pragma unroll
            for (int r = 0; r < 4; r++) acc[mt][nt][r] = 0.f;

    // ------- async stage loader -------
    auto load_stage = [&](int c, int stage) {
        const int kbase = c * 32;
        const uint32_t stbase = sb + stage * STAGE_BYTES;
        #pragma unroll
        for (int i = 0; i < 2; i++) {
            const int qd = tid + i * 256;         // 0..511
            const int row = qd >> 2;              // 0..127
            const int q = qd & 3;                 // 16B quad within 64B of data
            const uint32_t so = stbase + row * 80 + q * 16;
            const size_t ao = (size_t)(rowBase + row) * K + kbase + q * 8;
            const size_t bo = (size_t)(colBase + row) * K + kbase + q * 8;
            CP_ASYNC16(so + OFF_A_HI, Ah + ao);
            CP_ASYNC16(so + OFF_A_LO, Al + ao);
            CP_ASYNC16(so + OFF_B_HI, Bh + bo);
            CP_ASYNC16(so + OFF_B_LO, Bl + bo);
        }
        CP_COMMIT();
    };

    const int nChunks = K >> 5;
    load_stage(0, 0);

    // ldmatrix lane address components (constant across chunks)
    const uint32_t a_row = warp_m * 64 + (lane & 15);
    const uint32_t a_kadd = (lane >> 4) * 8;
    const uint32_t b_row = warp_n * 32 + (lane & 7) + ((lane >> 4) << 3);
    const uint32_t b_kadd = ((lane >> 3) & 1) * 8;

    for (int c = 0; c < nChunks; c++) {
        if (c + 1 < nChunks) { load_stage(c + 1, (c + 1) & 1); CP_WAIT1(); }
        else { CP_WAIT0(); }
        __syncthreads();

        const uint32_t st = sb + (c & 1) * STAGE_BYTES;

        #pragma unroll
        for (int ks = 0; ks < 2; ks++) {
            const uint32_t a_off = a_row * 80 + (ks * 16 + a_kadd) * 2;
            const uint32_t b_off = b_row * 80 + (ks * 16 + b_kadd) * 2;

            uint32_t a[4][4], bh[8], bl[8];
            // A_hi fragments (4 m-tiles)
            #pragma unroll
            for (int mt = 0; mt < 4; mt++)
                LDSM_X4(a[mt][0], a[mt][1], a[mt][2], a[mt][3],
                        st + OFF_A_HI + a_off + mt * (16 * 80));
            // B_hi fragments (4 n-tiles in 2 x4 loads)
            LDSM_X4(bh[0], bh[1], bh[2], bh[3], st + OFF_B_HI + b_off);
            LDSM_X4(bh[4], bh[5], bh[6], bh[7], st + OFF_B_HI + b_off + 16 * 80);
            // B_lo fragments
            LDSM_X4(bl[0], bl[1], bl[2], bl[3], st + OFF_B_LO + b_off);
            LDSM_X4(bl[4], bl[5], bl[6], bl[7], st + OFF_B_LO + b_off + 16 * 80);

            // pass hh + hl
            #pragma unroll
            for (int mt = 0; mt < 4; mt++)
                #pragma unroll
                for (int nt = 0; nt < 4; nt++) {
                    MMA_BF16(acc[mt][nt], a[mt], bh[nt * 2], bh[nt * 2 + 1]);
                    MMA_BF16(acc[mt][nt], a[mt], bl[nt * 2], bl[nt * 2 + 1]);
                }
            // A_lo fragments (reuse regs), pass lh
            #pragma unroll
            for (int mt = 0; mt < 4; mt++)
                LDSM_X4(a[mt][0], a[mt][1], a[mt][2], a[mt][3],
                        st + OFF_A_LO + a_off + mt * (16 * 80));
            #pragma unroll
            for (int mt = 0; mt < 4; mt++)
                #pragma unroll
                for (int nt = 0; nt < 4; nt++)
                    MMA_BF16(acc[mt][nt], a[mt], bh[nt * 2], bh[nt * 2 + 1]);
        }
        __syncthreads();
    }

    // ------- epilogue -------
    #pragma unroll
    for (int mt = 0; mt < 4; mt++) {
        const int r0 = rowBase + warp_m * 64 + mt * 16 + (lane >> 2);
        const int r1 = r0 + 8;
        #pragma unroll
        for (int nt = 0; nt < 4; nt++) {
            const int col = colBase + warp_n * 32 + nt * 8 + (lane & 3) * 2;
            float v0 = acc[mt][nt][0], v1 = acc[mt][nt][1];
            float v2 = acc[mt][nt][2], v3 = acc[mt][nt][3];
            if (EPI == EPI_BIAS_RESID || EPI == EPI_BIAS_GELU) {
                const float b0 = __ldg(bias + col), b1 = __ldg(bias + col + 1);
                v0 += b0; v1 += b1; v2 += b0; v3 += b1;
            }
            if (EPI == EPI_QKV) {
                // scale q columns by 1/8 (exact), k/v unscaled; write split bf16
                const float sc = (col < DIM) ? 0.125f : 1.0f;
                v0 *= sc; v1 *= sc; v2 *= sc; v3 *= sc;
                __nv_bfloat16 h0, h1, h2, h3, l0, l1, l2, l3;
                split_bf16(v0, h0, l0); split_bf16(v1, h1, l1);
                split_bf16(v2, h2, l2); split_bf16(v3, h3, l3);
                *reinterpret_cast<__nv_bfloat162*>(Ch + (size_t)r0 * N + col) = __halves2bfloat162(h0, h1);
                *reinterpret_cast<__nv_bfloat162*>(Cl + (size_t)r0 * N + col) = __halves2bfloat162(l0, l1);
                *reinterpret_cast<__nv_bfloat162*>(Ch + (size_t)r1 * N + col) = __halves2bfloat162(h2, h3);
                *reinterpret_cast<__nv_bfloat162*>(Cl + (size_t)r1 * N + col) = __halves2bfloat162(l2, l3);
            } else if (EPI == EPI_BIAS_GELU) {
                v0 = 0.5f * v0 * (1.f + erff(v0 * 0.70710678118654752f));
                v1 = 0.5f * v1 * (1.f + erff(v1 * 0.70710678118654752f));
                v2 = 0.5f * v2 * (1.f + erff(v2 * 0.70710678118654752f));
                v3 = 0.5f * v3 * (1.f + erff(v3 * 0.70710678118654752f));
                __nv_bfloat16 h0, h1, h2, h3, l0, l1, l2, l3;
                split_bf16(v0, h0, l0); split_bf16(v1, h1, l1);
                split_bf16(v2, h2, l2); split_bf16(v3, h3, l3);
                *reinterpret_cast<__nv_bfloat162*>(Ch + (size_t)r0 * N + col) = __halves2bfloat162(h0, h1);
                *reinterpret_cast<__nv_bfloat162*>(Cl + (size_t)r0 * N + col) = __halves2bfloat162(l0, l1);
                *reinterpret_cast<__nv_bfloat162*>(Ch + (size_t)r1 * N + col) = __halves2bfloat162(h2, h3);
                *reinterpret_cast<__nv_bfloat162*>(Cl + (size_t)r1 * N + col) = __halves2bfloat162(l2, l3);
            } else {
                if (EPI == EPI_BIAS_RESID) {
                    const float2 ra = *reinterpret_cast<const float2*>(R + (size_t)r0 * N + col);
                    const float2 rb = *reinterpret_cast<const float2*>(R + (size_t)r1 * N + col);
                    v0 += ra.x; v1 += ra.y; v2 += rb.x; v3 += rb.y;
                }
                float2 p0; p0.x = v0; p0.y = v1;
                float2 p1; p1.x = v2; p1.y = v3;
                *reinterpret_cast<float2*>(Cf + (size_t)r0 * N + col) = p0;
                *reinterpret_cast<float2*>(Cf + (size_t)r1 * N + col) = p1;
            }
        }
    }
}

// ==================== Flash attention (tensor-core, split-bf16) ============
// CTA: 128 q-rows x 64 kv per iter, 8 warps x 16 q-rows. Causal.
// Inputs: qkv_hi/lo [MROWS][3*DIM] bf16 (q pre-scaled by 1/8).
#define FROWB 144                                // bytes per smem row (64 bf16 + pad)
#define FQ_HI 0
#define FQ_LO (128*FROWB)                        // 18432
#define FSTAGE0 (2*128*FROWB)                    // 36864
#define FS_K_HI 0
#define FS_K_LO (64*FROWB)
#define FS_V_HI (2*64*FROWB)
#define FS_V_LO (3*64*FROWB)
#define FSTAGE_BYTES (4*64*FROWB)                // 36864
#define FLASH_SMEM (FSTAGE0 + 2*FSTAGE_BYTES)    // 110592

__global__ void __launch_bounds__(256, 1)
flash_tc_kernel(const __nv_bfloat16* __restrict__ qh,
                const __nv_bfloat16* __restrict__ ql,
                __nv_bfloat16* __restrict__ ohi, __nv_bfloat16* __restrict__ olo)
{
    extern __shared__ char smem[];
    const uint32_t sb = smem_u32(smem);
    const int qb = blockIdx.x;          // q-tile 0..15
    const int bh = blockIdx.y;          // 0..63
    const int b = bh >> 4, h = bh & 15;
    const int tid = threadIdx.x;
    const int lane = tid & 31, w = tid >> 5;
    const int rowStride = 3 * DIM;

    // load Q (hi/lo) 128x64
    #pragma unroll
    for (int i = 0; i < 4; i++) {
        const int c = tid + i * 256;
        const int r = c >> 3, q = c & 7;
        const uint32_t so = r * FROWB + q * 16;
        const size_t go = (size_t)(b * SEQ + qb * 128 + r) * rowStride + h * HDIM + q * 8;
        CP_ASYNC16(sb + FQ_HI + so, qh + go);
        CP_ASYNC16(sb + FQ_LO + so, ql + go);
    }

    const int nkv = 2 * qb + 2;
    auto load_kv = [&](int j, int buf) {
        const uint32_t stb = sb + FSTAGE0 + buf * FSTAGE_BYTES;
        #pragma unroll
        for (int i = 0; i < 2; i++) {
            const int c = tid + i * 256;
            const int r = c >> 3, q = c & 7;
            const uint32_t so = r * FROWB + q * 16;
            const size_t gk = (size_t)(b * SEQ + j * 64 + r) * rowStride + DIM + h * HDIM + q * 8;
            const size_t gv = gk + DIM;
            CP_ASYNC16(stb + FS_K_HI + so, qh + gk);
            CP_ASYNC16(stb + FS_K_LO + so, ql + gk);
            CP_ASYNC16(stb + FS_V_HI + so, qh + gv);
            CP_ASYNC16(stb + FS_V_LO + so, ql + gv);
        }
    };
    load_kv(0, 0);
    CP_COMMIT();

    float O[8][4];
    #pragma unroll
    for (int nt = 0; nt < 8; nt++)
        #pragma unroll
        for (int r = 0; r < 4; r++) O[nt][r] = 0.f;
    float m0 = -1e30f, m1 = -1e30f, l0 = 0.f, l1 = 0.f;

    const int qr0 = qb * 128 + w * 16 + (lane >> 2);   // global q row (and +8)

    // ldmatrix address components
    const int t8 = lane >> 3;
    const uint32_t q_row_off = (w * 16 + (lane & 15)) * FROWB;
    const uint32_t q_kadd = (lane >> 4) * 8;
    const uint32_t k_row = (t8 >> 1) * 8 + (lane & 7);
    const uint32_t k_hd = (t8 & 1) * 8;
    const uint32_t v_kv = (t8 & 1) * 8 + (lane & 7);
    const uint32_t v_nc = (t8 >> 1) * 8;

    for (int j = 0; j < nkv; j++) {
        if (j + 1 < nkv) { load_kv(j + 1, (j + 1) & 1); CP_COMMIT(); CP_WAIT1(); }
        else { CP_WAIT0(); }
        __syncthreads();
        const uint32_t st = sb + FSTAGE0 + (j & 1) * FSTAGE_BYTES;

        // ---- S = Q K^T (3-pass split) ----
        float s[8][4];
        #pragma unroll
        for (int nt = 0; nt < 8; nt++)
            #pragma unroll
            for (int r = 0; r < 4; r++) s[nt][r] = 0.f;

        #pragma unroll
        for (int ks = 0; ks < 4; ks++) {
            const uint32_t qoff = q_row_off + (ks * 16 + q_kadd) * 2;
            uint32_t a[4];
            LDSM_X4(a[0], a[1], a[2], a[3], sb + FQ_HI + qoff);
            uint32_t kh[4][4], kl[4][4];
            #pragma unroll
            for (int g = 0; g < 4; g++) {
                const uint32_t koff = (g * 16 + k_row) * FROWB + (ks * 16 + k_hd) * 2;
                LDSM_X4(kh[g][0], kh[g][1], kh[g][2], kh[g][3], st + FS_K_HI + koff);
                LDSM_X4(kl[g][0], kl[g][1], kl[g][2], kl[g][3], st + FS_K_LO + koff);
            }
            #pragma unroll
            for (int g = 0; g < 4; g++) {
                MMA_BF16(s[2 * g],     a, kh[g][0], kh[g][1]);
                MMA_BF16(s[2 * g + 1], a, kh[g][2], kh[g][3]);
                MMA_BF16(s[2 * g],     a, kl[g][0], kl[g][1]);
                MMA_BF16(s[2 * g + 1], a, kl[g][2], kl[g][3]);
            }
            LDSM_X4(a[0], a[1], a[2], a[3], sb + FQ_LO + qoff);
            #pragma unroll
            for (int g = 0; g < 4; g++) {
                MMA_BF16(s[2 * g],     a, kh[g][0], kh[g][1]);
                MMA_BF16(s[2 * g + 1], a, kh[g][2], kh[g][3]);
            }
        }

        // ---- causal mask (only the two diagonal-straddling tiles) ----
        if (j >= 2 * qb) {
            const int kvb = j * 64;
            #pragma unroll
            for (int nt = 0; nt < 8; nt++) {
                const int kc = kvb + nt * 8 + (lane & 3) * 2;
                if (kc     > qr0)     s[nt][0] = -1e30f;
                if (kc + 1 > qr0)     s[nt][1] = -1e30f;
                if (kc     > qr0 + 8) s[nt][2] = -1e30f;
                if (kc + 1 > qr0 + 8) s[nt][3] = -1e30f;
            }
        }

        // ---- online softmax (rows r and r+8) ----
        float mx0 = -1e30f, mx1 = -1e30f;
        #pragma unroll
        for (int nt = 0; nt < 8; nt++) {
            mx0 = fmaxf(mx0, fmaxf(s[nt][0], s[nt][1]));
            mx1 = fmaxf(mx1, fmaxf(s[nt][2], s[nt][3]));
        }
        mx0 = fmaxf(mx0, __shfl_xor_sync(0xffffffffu, mx0, 1));
        mx0 = fmaxf(mx0, __shfl_xor_sync(0xffffffffu, mx0, 2));
        mx1 = fmaxf(mx1, __shfl_xor_sync(0xffffffffu, mx1, 1));
        mx1 = fmaxf(mx1, __shfl_xor_sync(0xffffffffu, mx1, 2));
        const float nm0 = fmaxf(m0, mx0), nm1 = fmaxf(m1, mx1);
        const float sc0 = __expf(m0 - nm0), sc1 = __expf(m1 - nm1);
        m0 = nm0; m1 = nm1;
        float r0 = 0.f, r1 = 0.f;
        #pragma unroll
        for (int nt = 0; nt < 8; nt++) {
            s[nt][0] = __expf(s[nt][0] - nm0); r0 += s[nt][0];
            s[nt][1] = __expf(s[nt][1] - nm0); r0 += s[nt][1];
            s[nt][2] = __expf(s[nt][2] - nm1); r1 += s[nt][2];
            s[nt][3] = __expf(s[nt][3] - nm1); r1 += s[nt][3];
        }
        r0 += __shfl_xor_sync(0xffffffffu, r0, 1);
        r0 += __shfl_xor_sync(0xffffffffu, r0, 2);
        r1 += __shfl_xor_sync(0xffffffffu, r1, 1);
        r1 += __shfl_xor_sync(0xffffffffu, r1, 2);
        l0 = l0 * sc0 + r0;
        l1 = l1 * sc1 + r1;
        #pragma unroll
        for (int nt = 0; nt < 8; nt++) {
            O[nt][0] *= sc0; O[nt][1] *= sc0;
            O[nt][2] *= sc1; O[nt][3] *= sc1;
        }

        // ---- O += P V (3-pass split) ----
        #pragma unroll
        for (int ks = 0; ks < 4; ks++) {
            const int t0 = 2 * ks, t1 = 2 * ks + 1;
            uint32_t phi[4], plo[4];
            pack_split2(s[t0][0], s[t0][1], phi[0], plo[0]);
            pack_split2(s[t0][2], s[t0][3], phi[1], plo[1]);
            pack_split2(s[t1][0], s[t1][1], phi[2], plo[2]);
            pack_split2(s[t1][2], s[t1][3], phi[3], plo[3]);
            uint32_t vh[4][4], vl[4][4];
            #pragma unroll
            for (int g = 0; g < 4; g++) {
                const uint32_t voff = (ks * 16 + v_kv) * FROWB + (g * 16 + v_nc) * 2;
                LDSM_X4_T(vh[g][0], vh[g][1], vh[g][2], vh[g][3], st + FS_V_HI + voff);
                LDSM_X4_T(vl[g][0], vl[g][1], vl[g][2], vl[g][3], st + FS_V_LO + voff);
            }
            #pragma unroll
            for (int g = 0; g < 4; g++) {
                MMA_BF16(O[2 * g],     phi, vh[g][0], vh[g][1]);
                MMA_BF16(O[2 * g + 1], phi, vh[g][2], vh[g][3]);
                MMA_BF16(O[2 * g],     phi, vl[g][0], vl[g][1]);
                MMA_BF16(O[2 * g + 1], phi, vl[g][2], vl[g][3]);
                MMA_BF16(O[2 * g],     plo, vh[g][0], vh[g][1]);
                MMA_BF16(O[2 * g + 1], plo, vh[g][2], vh[g][3]);
            }
        }
        __syncthreads();
    }

    // ---- epilogue: normalize, split, store ----
    const float il0 = 1.f / l0, il1 = 1.f / l1;
    const size_t gr0 = (size_t)(b * SEQ + qr0) * DIM + h * HDIM;
    const size_t gr1 = gr0 + 8 * DIM;
    #pragma unroll
    for (int nt = 0; nt < 8; nt++) {
        const int col = nt * 8 + (lane & 3) * 2;
        float v0 = O[nt][0] * il0, v1 = O[nt][1] * il0;
        float v2 = O[nt][2] * il1, v3 = O[nt][3] * il1;
        __nv_bfloat16 h0, h1, h2, h3, l0b, l1b, l2b, l3b;
        split_bf16(v0, h0, l0b); split_bf16(v1, h1, l1b);
        split_bf16(v2, h2, l2b); split_bf16(v3, h3, l3b);
        *reinterpret_cast<__nv_bfloat162*>(ohi + gr0 + col) = __halves2bfloat162(h0, h1);
        *reinterpret_cast<__nv_bfloat162*>(olo + gr0 + col) = __halves2bfloat162(l0b, l1b);
        *reinterpret_cast<__nv_bfloat162*>(ohi + gr1 + col) = __halves2bfloat162(h2, h3);
        *reinterpret_cast<__nv_bfloat162*>(olo + gr1 + col) = __halves2bfloat162(l2b, l3b);
    }
}

// ==================== launch ================================================
extern "C" void kernel_launch(void* const* d_in, const int* in_sizes, int n_in,
                              void* d_out, int out_size)
{
    (void)in_sizes; (void)n_in; (void)out_size;
    const float* x     = (const float*)d_in[0];
    const float* ln1_g = (const float*)d_in[2];
    const float* ln1_b = (const float*)d_in[3];
    const float* ln2_g = (const float*)d_in[4];
    const float* ln2_b = (const float*)d_in[5];
    const float* qkv_w = (const float*)d_in[6];
    const float* out_w = (const float*)d_in[7];
    const float* out_b = (const float*)d_in[8];
    const float* fc1_w = (const float*)d_in[9];
    const float* fc1_b = (const float*)d_in[10];
    const float* fc2_w = (const float*)d_in[11];
    const float* fc2_b = (const float*)d_in[12];
    float* out = (float*)d_out;

    float *x2;
    __nv_bfloat16 *qkv_hi, *qkv_lo, *h_hi, *h_lo, *att_hi, *att_lo, *ffn_hi, *ffn_lo;
    __nv_bfloat16 *wq_hi, *wq_lo, *wo_hi, *wo_lo, *w1_hi, *w1_lo, *w2_hi, *w2_lo;
    cudaGetSymbolAddress((void**)&x2,     g_x2);
    cudaGetSymbolAddress((void**)&qkv_hi, g_qkv_hi);
    cudaGetSymbolAddress((void**)&qkv_lo, g_qkv_lo);
    cudaGetSymbolAddress((void**)&h_hi,   g_h_hi);
    cudaGetSymbolAddress((void**)&h_lo,   g_h_lo);
    cudaGetSymbolAddress((void**)&att_hi, g_att_hi);
    cudaGetSymbolAddress((void**)&att_lo, g_att_lo);
    cudaGetSymbolAddress((void**)&ffn_hi, g_ffn_hi);
    cudaGetSymbolAddress((void**)&ffn_lo, g_ffn_lo);
    cudaGetSymbolAddress((void**)&wq_hi,  g_wq_hi);
    cudaGetSymbolAddress((void**)&wq_lo,  g_wq_lo);
    cudaGetSymbolAddress((void**)&wo_hi,  g_wo_hi);
    cudaGetSymbolAddress((void**)&wo_lo,  g_wo_lo);
    cudaGetSymbolAddress((void**)&w1_hi,  g_w1_hi);
    cudaGetSymbolAddress((void**)&w1_lo,  g_w1_lo);
    cudaGetSymbolAddress((void**)&w2_hi,  g_w2_hi);
    cudaGetSymbolAddress((void**)&w2_lo,  g_w2_lo);

    cudaFuncSetAttribute(flash_tc_kernel,
                         cudaFuncAttributeMaxDynamicSharedMemorySize, FLASH_SMEM);
    cudaFuncSetAttribute(tc_gemm_kernel<EPI_QKV>,
                         cudaFuncAttributeMaxDynamicSharedMemorySize, GEMM_SMEM);
    cudaFuncSetAttribute(tc_gemm_kernel<EPI_BIAS_RESID>,
                         cudaFuncAttributeMaxDynamicSharedMemorySize, GEMM_SMEM);
    cudaFuncSetAttribute(tc_gemm_kernel<EPI_BIAS_GELU>,
                         cudaFuncAttributeMaxDynamicSharedMemorySize, GEMM_SMEM);

    // 0. weight transpose + split
    wsplit_kernel<<<dim3(3 * DIM / 32, DIM / 32), 256>>>(qkv_w, wq_hi, wq_lo, DIM, 3 * DIM);
    wsplit_kernel<<<dim3(DIM / 32, DIM / 32), 256>>>(out_w, wo_hi, wo_lo, DIM, DIM);
    wsplit_kernel<<<dim3(FFDIM / 32, DIM / 32), 256>>>(fc1_w, w1_hi, w1_lo, DIM, FFDIM);
    wsplit_kernel<<<dim3(DIM / 32, FFDIM / 32), 256>>>(fc2_w, w2_hi, w2_lo, FFDIM, DIM);

    // 1. LN1 -> h (bf16 hi/lo)
    ln_kernel<<<MROWS, 256>>>(x, ln1_g, ln1_b, h_hi, h_lo);
    // 2. qkv = h @ qkv_w  [8192 x 3072 x 1024]  (split-bf16 out, q scaled 1/8)
    tc_gemm_kernel<EPI_QKV><<<dim3(3 * DIM / 128, MROWS / 128), 256, GEMM_SMEM>>>(
        h_hi, h_lo, wq_hi, wq_lo, nullptr, nullptr, nullptr, qkv_hi, qkv_lo, 3 * DIM, DIM);
    // 3. attention -> att (bf16 hi/lo)
    flash_tc_kernel<<<dim3(SEQ / 128, BATCH * NHEAD), 256, FLASH_SMEM>>>(
        qkv_hi, qkv_lo, att_hi, att_lo);
    // 4. x2 = x + att @ out_w + out_b  [8192 x 1024 x 1024]
    tc_gemm_kernel<EPI_BIAS_RESID><<<dim3(DIM / 128, MROWS / 128), 256, GEMM_SMEM>>>(
        att_hi, att_lo, wo_hi, wo_lo, out_b, x, x2, nullptr, nullptr, DIM, DIM);
    // 5. LN2 -> h (bf16 hi/lo)
    ln_kernel<<<MROWS, 256>>>(x2, ln2_g, ln2_b, h_hi, h_lo);
    // 6. ffn = gelu(h @ fc1_w + fc1_b)  [8192 x 4096 x 1024]  (bf16 hi/lo out)
    tc_gemm_kernel<EPI_BIAS_GELU><<<dim3(FFDIM / 128, MROWS / 128), 256, GEMM_SMEM>>>(
        h_hi, h_lo, w1_hi, w1_lo, fc1_b, nullptr, nullptr, ffn_hi, ffn_lo, FFDIM, DIM);
    // 7. out = x2 + ffn @ fc2_w + fc2_b  [8192 x 1024 x 4096]
    tc_gemm_kernel<EPI_BIAS_RESID><<<dim3(DIM / 128, MROWS / 128), 256, GEMM_SMEM>>>(
        ffn_hi, ffn_lo, w2_hi, w2_lo, fc2_b, x2, out, nullptr, nullptr, DIM, FFDIM);
}